// round 16
// baseline (speedup 1.0000x reference)
#include <cuda_runtime.h>
#include <cstdint>

// Problem constants
#define DD   256
#define HW   4096
#define NN   32768
#define KK   8192
#define NTILES 32          // K tiles of 256 codes
#define EPS  2.5e-4f

// Scratch (no cudaMalloc allowed)
__device__ __align__(16) float g_A[(size_t)NN * DD];   // fragment-packed A (32 MB)
__device__ __align__(16) float g_B[(size_t)KK * DD];   // fragment-packed B (8 MB)
__device__ __align__(16) float g_X[(size_t)NN * DD];   // row-major pixels (32 MB)
__device__ __align__(16) float g_cbsq[KK];
__device__ float g_xsq[NN];
__device__ float g_pv[NTILES * NN];                    // per-(tile,pixel) tc-min
__device__ ulonglong4 g_mask[(size_t)NTILES * NN];     // 256-bit candidate masks (32 MB)

#define OFF_ZQ1 ((size_t)0)
#define OFF_ZQ2 ((size_t)NN * DD)
#define OFF_LOG ((size_t)2 * NN * DD)

#define STAGE_F 12288                  // floats per stage (A 4096 + B 8192)
#define MBA_OFF 147456                 // bytes: full[3] then empty[3] mbarriers
#define SMEM_BYTES 147520

// ---------------- helpers ----------------
__device__ __forceinline__ uint32_t smem_u32(const void* p) {
    uint32_t a;
    asm("{ .reg .u64 t; cvta.to.shared.u64 t, %1; cvt.u32.u64 %0, t; }" : "=r"(a) : "l"(p));
    return a;
}

// bulk async copy gmem->smem, completion via mbarrier complete_tx
__device__ __forceinline__ void bulk_cp(uint32_t dst, const float* src,
                                        uint32_t bytes, uint32_t mbar) {
    asm volatile(
        "cp.async.bulk.shared::cluster.global.mbarrier::complete_tx::bytes "
        "[%0], [%1], %2, [%3];"
        :: "r"(dst), "l"(src), "r"(bytes), "r"(mbar) : "memory");
}
#define MBARRIER_INIT(addr, count) \
    asm volatile("mbarrier.init.shared.b64 [%0], %1;" \
        :: "r"((uint32_t)(addr)), "r"((uint32_t)(count)) : "memory")
#define MBARRIER_EXPECT_TX(addr, bytes) \
    asm volatile("mbarrier.arrive.expect_tx.shared.b64 _, [%0], %1;" \
        :: "r"((uint32_t)(addr)), "r"((uint32_t)(bytes)) : "memory")
#define MBARRIER_ARRIVE(addr) \
    asm volatile("mbarrier.arrive.release.cta.shared.b64 _, [%0];" \
        :: "r"((uint32_t)(addr)) : "memory")
#define MBARRIER_WAIT_PARITY(mbar_smem_addr, phase_parity) do { \
    uint32_t _mbar = (uint32_t)(mbar_smem_addr); \
    uint32_t _parity = (uint32_t)(phase_parity); \
    uint32_t _done; \
    asm volatile( \
        "{\n\t.reg .pred p;\n\t" \
        "mbarrier.try_wait.parity.acquire.cta.shared::cta.b64 p, [%1], %2;\n\t" \
        "selp.b32 %0, 1, 0, p;\n\t}" \
        : "=r"(_done) : "r"(_mbar), "r"(_parity) : "memory"); \
    if (!_done) { \
        asm volatile( \
            "{\n\t.reg .pred P1;\n\t" \
            "WAIT_LOOP_%=:\n\t" \
            "mbarrier.try_wait.parity.acquire.cta.shared::cta.b64 P1, [%0], %1, 0x989680;\n\t" \
            "@P1 bra.uni WAIT_DONE_%=;\n\t" \
            "bra.uni WAIT_LOOP_%=;\n\t" \
            "WAIT_DONE_%=:\n\t}" \
            :: "r"(_mbar), "r"(_parity) : "memory"); \
    } \
} while(0)

// tf32 mma: D = A(16x8 row) * B(8x8 col) + D
__device__ __forceinline__ void mma_tf32(float* c, const uint32_t* a, const uint32_t* b) {
    asm volatile(
        "mma.sync.aligned.m16n8k8.row.col.f32.tf32.tf32.f32 "
        "{%0,%1,%2,%3}, {%4,%5,%6,%7}, {%8,%9}, {%0,%1,%2,%3};"
        : "+f"(c[0]), "+f"(c[1]), "+f"(c[2]), "+f"(c[3])
        : "r"(a[0]), "r"(a[1]), "r"(a[2]), "r"(a[3]), "r"(b[0]), "r"(b[1]));
}

// swizzled float index inside the [128 px][256 col] staging buffer
__device__ __forceinline__ int stg_idx(int px, int col) {
    return px * 256 + (((col >> 2) ^ (px & 63)) << 2) + (col & 3);
}

// ---------------- prep kernels ----------------

// Per block: 64 pixels. Emits g_X rows + g_A fragment layout + g_xsq.
__global__ void vq_prep(const float* __restrict__ z) {
    __shared__ float s[64 * 257];
    __shared__ float ps[256];
    const int t = threadIdx.x;
    const int mtile = blockIdx.x >> 1, wm = blockIdx.x & 1;
    const int p0 = mtile * 128 + wm * 64;
    const int b = p0 >> 12, hw0 = p0 & 4095;
    const float* zb = z + (size_t)b * DD * HW + hw0;
#pragma unroll 8
    for (int i = 0; i < 64; i++) {
        int idx = i * 256 + t;
        int d = idx >> 6, px = idx & 63;
        s[px * 257 + d] = zb[(size_t)d * HW + px];
    }
    __syncthreads();
    // xsq: 4-way split per pixel (uniform per-pixel shift -> argmin-safe)
    {
        int p = t >> 2, q = t & 3;
        const float* row = s + p * 257 + q * 64;
        float acc = 0.f;
#pragma unroll 8
        for (int i = 0; i < 64; i++) acc = fmaf(row[i], row[i], acc);
        ps[t] = acc;
    }
    // row-major copy
    float* gx = g_X + (size_t)p0 * DD;
#pragma unroll 8
    for (int i = 0; i < 64; i++)
        gx[(size_t)i * DD + t] = s[i * 257 + t];
    // fragment-packed copy
#pragma unroll
    for (int w = 0; w < 16; w++) {
        int pos = w * 256 + t;              // float4 position 0..4095
        int lane = pos & 31;
        int kk = (pos >> 5) & 3;
        int i = (pos >> 7) & 3;
        int c = pos >> 9;                   // chunk 0..7
        int rl = i * 16 + (lane >> 2);
        int col = c * 32 + kk * 8 + (lane & 3);
        float4 v;
        v.x = s[rl * 257 + col];
        v.y = s[(rl + 8) * 257 + col];
        v.z = s[rl * 257 + col + 4];
        v.w = s[(rl + 8) * 257 + col + 4];
        float* dst = g_A + ((size_t)(mtile * 8 + c)) * 4096
                   + ((wm * 4 + i) * 4 + kk) * 128 + lane * 4;
        *(float4*)dst = v;
    }
    __syncthreads();
    if (t < 64)
        g_xsq[p0 + t] = ((ps[t * 4] + ps[t * 4 + 1]) + ps[t * 4 + 2]) + ps[t * 4 + 3];
}

// g_B: [ntile(32)][chunk(8)] 32KB blocks; float2 at ((wj*4+kk)*32+lane), wj 0..31
__global__ void vq_packB(const float* __restrict__ cb) {
    const int t = threadIdx.x;
    const int nt = blockIdx.x >> 3, c = blockIdx.x & 7;
    const int k0 = nt * 256;
    float* dst = g_B + (size_t)blockIdx.x * 8192;
#pragma unroll
    for (int w = 0; w < 16; w++) {
        int pos = w * 256 + t;              // float2 position 0..4095
        int lane = pos & 31;
        int kk = (pos >> 5) & 3;
        int wj = pos >> 7;                  // 8-code group 0..31
        int rb = wj * 8 + (lane >> 2);
        int kc = c * 32 + kk * 8 + (lane & 3);
        const float* src = cb + (size_t)(k0 + rb) * DD + kc;
        *(float2*)(dst + pos * 2) = make_float2(src[0], src[4]);
    }
}

// warp-per-code ||c||^2
__global__ void vq_cbsq(const float* __restrict__ cb) {
    int w = (blockIdx.x * 256 + threadIdx.x) >> 5;
    int lane = threadIdx.x & 31;
    const float* r = cb + (size_t)w * DD + lane;
    float s = 0.f;
#pragma unroll
    for (int i = 0; i < 8; i++) { float v = r[i * 32]; s = fmaf(v, v, s); }
#pragma unroll
    for (int o = 16; o > 0; o >>= 1)
        s += __shfl_xor_sync(0xffffffffu, s, o);
    if (lane == 0) g_cbsq[w] = s;
}

// ---------------- tf32 mma.sync GEMM + logits + tile min/mask ----------------
// grid (256 m-tiles, 32 n-tiles), 256 threads (8 warps: 2 m x 4 n, warp 64x64)
// 1 CTA/SM; barrier-free mainloop (full/empty mbarrier ring, bulk_cp fills),
// software-pipelined fragments.
__global__ void __launch_bounds__(256, 1)
vq_gemm(const float* __restrict__ cb, float* __restrict__ out) {
    extern __shared__ float sm[];
    const int tid = threadIdx.x, lane = tid & 31, wid = tid >> 5;
    const int wm = wid & 1, wn = wid >> 1;
    const int mtile = blockIdx.x, ntile = blockIdx.y;
    const int n0 = mtile * 128, k0 = ntile * 256;
    const int b = n0 >> 12, hw0 = n0 & 4095;
    const uint32_t sb = smem_u32(sm);

    const float* gAb = g_A + (size_t)mtile * 8 * 4096;
    const float* gBb = g_B + (size_t)ntile * 8 * 8192;

    if (tid == 0) {
#pragma unroll
        for (int s = 0; s < 3; s++) {
            MBARRIER_INIT(sb + MBA_OFF + s * 8, 1);        // full (tx-based)
            MBARRIER_INIT(sb + MBA_OFF + 24 + s * 8, 8);   // empty (8 warp arrivals)
        }
    }
    __syncthreads();

    auto issue = [&](int c) {
        uint32_t base = sb + (uint32_t)(c % 3) * (STAGE_F * 4);
        uint32_t mb = sb + MBA_OFF + (c % 3) * 8;
        MBARRIER_EXPECT_TX(mb, 49152u);
        bulk_cp(base,         gAb + (size_t)c * 4096, 16384u, mb);
        bulk_cp(base + 16384, gBb + (size_t)c * 8192, 32768u, mb);
    };
    if (tid == 0) { issue(0); issue(1); issue(2); }

    float acc[4][8][4];
#pragma unroll
    for (int i = 0; i < 4; i++)
#pragma unroll
        for (int j = 0; j < 8; j++)
#pragma unroll
            for (int r = 0; r < 4; r++) acc[i][j][r] = 0.f;

#pragma unroll
    for (int c = 0; c < 8; c++) {
        const int s = c % 3;
        const int par = (c / 3) & 1;
        MBARRIER_WAIT_PARITY(sb + MBA_OFF + s * 8, par);
        const float* As = sm + s * STAGE_F;
        const float* Bs = As + 4096;

        uint4 af[2][4]; uint2 bf[2][8];
#pragma unroll
        for (int i = 0; i < 4; i++)
            af[0][i] = *(const uint4*)(As + ((wm * 4 + i) * 4 + 0) * 128 + lane * 4);
#pragma unroll
        for (int j = 0; j < 8; j++)
            bf[0][j] = *(const uint2*)(Bs + ((wn * 8 + j) * 4 + 0) * 64 + lane * 2);

#pragma unroll
        for (int kk = 0; kk < 4; kk++) {
            const int cur = kk & 1, nxt = cur ^ 1;
            if (kk < 3) {
#pragma unroll
                for (int i = 0; i < 4; i++)
                    af[nxt][i] = *(const uint4*)(As + ((wm * 4 + i) * 4 + kk + 1) * 128 + lane * 4);
#pragma unroll
                for (int j = 0; j < 8; j++)
                    bf[nxt][j] = *(const uint2*)(Bs + ((wn * 8 + j) * 4 + kk + 1) * 64 + lane * 2);
            }
#pragma unroll
            for (int i = 0; i < 4; i++)
#pragma unroll
                for (int j = 0; j < 8; j++)
                    mma_tf32(acc[i][j], (const uint32_t*)&af[cur][i], (const uint32_t*)&bf[cur][j]);
        }
        if (lane == 0) MBARRIER_ARRIVE(sb + MBA_OFF + 24 + s * 8);
        if (c + 3 < 8 && tid == 0) {
            MBARRIER_WAIT_PARITY(sb + MBA_OFF + 24 + s * 8, par);
            issue(c + 3);
        }
    }
    __syncthreads();

    // phase 1: dump accumulators into smem staging [128 px][256 col] (swizzled)
#pragma unroll
    for (int i = 0; i < 4; i++) {
#pragma unroll
        for (int j = 0; j < 8; j++) {
            int px = wm * 64 + i * 16 + (lane >> 2);
            int col = wn * 64 + j * 8 + 2 * (lane & 3);
            *(float2*)&sm[stg_idx(px,     col)] = make_float2(acc[i][j][0], acc[i][j][1]);
            *(float2*)&sm[stg_idx(px + 8, col)] = make_float2(acc[i][j][2], acc[i][j][3]);
        }
    }
    __syncthreads();

    // phase 2: dist + coalesced logit stores + per-pixel min (half = 128 cols)
    const int px = tid & 127, half = tid >> 7;
    const float xsv = g_xsq[n0 + px];
    float* lb = out + OFF_LOG + ((size_t)b * KK + k0 + half * 128) * HW + hw0 + px;
    float bv = __int_as_float(0x7f800000);
#pragma unroll 8
    for (int cg = 0; cg < 32; cg++) {
        int slot = half * 32 + cg;
        float4 dv = *(const float4*)&sm[px * 256 + ((slot ^ (px & 63)) << 2)];
        float4 cq = *(const float4*)&g_cbsq[k0 + half * 128 + cg * 4];
        float d0 = fmaf(-2.f, dv.x, cq.x + xsv);
        float d1 = fmaf(-2.f, dv.y, cq.y + xsv);
        float d2 = fmaf(-2.f, dv.z, cq.z + xsv);
        float d3 = fmaf(-2.f, dv.w, cq.w + xsv);
        bv = fminf(bv, fminf(fminf(d0, d1), fminf(d2, d3)));
        __stcs(lb + (size_t)(cg * 4 + 0) * HW, -d0);
        __stcs(lb + (size_t)(cg * 4 + 1) * HW, -d1);
        __stcs(lb + (size_t)(cg * 4 + 2) * HW, -d2);
        __stcs(lb + (size_t)(cg * 4 + 3) * HW, -d3);
    }
    float* fv  = sm + 32768;   // [256]
    float* pvw = sm + 33024;   // [128] combined per-pixel min
    fv[tid] = bv;
    __syncthreads();
    if (tid < 128) {
        float comb = fminf(fv[tid], fv[128 + tid]);
        g_pv[(size_t)ntile * NN + n0 + tid] = comb;
        pvw[tid] = comb;
    }
    __syncthreads();

    // phase 3: candidate bitmask (codes with dtc <= tile_min + EPS); 128 bits/half
    const float thr = pvw[px] + EPS;
    unsigned long long m0 = 0, m1 = 0;
#pragma unroll 8
    for (int cg = 0; cg < 32; cg++) {
        int slot = half * 32 + cg;
        float4 dv = *(const float4*)&sm[px * 256 + ((slot ^ (px & 63)) << 2)];
        float4 cq = *(const float4*)&g_cbsq[k0 + half * 128 + cg * 4];
        float d0 = fmaf(-2.f, dv.x, cq.x + xsv);
        float d1 = fmaf(-2.f, dv.y, cq.y + xsv);
        float d2 = fmaf(-2.f, dv.z, cq.z + xsv);
        float d3 = fmaf(-2.f, dv.w, cq.w + xsv);
        unsigned long long* mp = (cg < 16) ? &m0 : &m1;
        int sh = (cg * 4) & 63;
        if (d0 <= thr) *mp |= 1ull << (sh + 0);
        if (d1 <= thr) *mp |= 1ull << (sh + 1);
        if (d2 <= thr) *mp |= 1ull << (sh + 2);
        if (d3 <= thr) *mp |= 1ull << (sh + 3);
    }
    unsigned long long* gm = (unsigned long long*)g_mask;
    size_t mo = ((size_t)ntile * NN + n0 + px) * 4 + half * 2;
    gm[mo] = m0; gm[mo + 1] = m1;
}

// ---------------- exact rescore of masked candidates + gather ----------------
// grid 512 blocks x 256 threads; 64 px/block, 4 threads per pixel (8 tiles each)
__global__ void __launch_bounds__(256)
vq_rescore(const float* __restrict__ cb, float* __restrict__ out) {
    __shared__ float Xs[64 * 260];
    __shared__ float lmv[4 * 64];
    __shared__ float bv4[4 * 64];
    __shared__ int   bk4[4 * 64];
    __shared__ int   sidx[64];
    const int t = threadIdx.x;
    const int n0 = blockIdx.x * 64;
    const int b = n0 >> 12, hw0 = n0 & 4095;
    const int px = t & 63, q = t >> 6;      // 4 threads per pixel
    const int n = n0 + px;

    const float4* gx = (const float4*)(g_X + (size_t)n0 * DD);
#pragma unroll
    for (int i = 0; i < 16; i++) {
        int idx = t + i * 256;
        int ppx = idx >> 6, qq = idx & 63;
        *(float4*)&Xs[ppx * 260 + qq * 4] = gx[ppx * 64 + qq];
    }

    // local min over this thread's 8 tiles
    float lm = __int_as_float(0x7f800000);
#pragma unroll
    for (int i = 0; i < 8; i++)
        lm = fminf(lm, g_pv[(size_t)(q * 8 + i) * NN + n]);
    lmv[q * 64 + px] = lm;
    __syncthreads();
    const float thresh = fminf(fminf(lmv[px], lmv[64 + px]),
                               fminf(lmv[128 + px], lmv[192 + px])) + EPS;

    // scan own 8 tiles for candidates, exact rescore
    const float xsv = g_xsq[n];
    const float* xr = &Xs[px * 260];
    float bestv = __int_as_float(0x7f800000);
    int bestk = 0x7fffffff;
#pragma unroll
    for (int i = 0; i < 8; i++) {
        int s = q * 8 + i;
        if (g_pv[(size_t)s * NN + n] <= thresh) {
            ulonglong4 mk = g_mask[(size_t)s * NN + n];
            unsigned long long mws[4] = {mk.x, mk.y, mk.z, mk.w};
#pragma unroll
            for (int w = 0; w < 4; w++) {
                unsigned long long mw = mws[w];
                while (mw) {
                    int j = __ffsll(mw) - 1;
                    mw &= mw - 1;
                    int k = s * 256 + w * 64 + j;
                    const float4* cv = (const float4*)(cb + (size_t)k * DD);
                    float s2 = 0.f;
#pragma unroll 8
                    for (int qq = 0; qq < 64; qq++) {
                        float4 a = *(const float4*)&xr[qq * 4];
                        float4 v = cv[qq];
                        s2 = fmaf(a.x, v.x, s2); s2 = fmaf(a.y, v.y, s2);
                        s2 = fmaf(a.z, v.z, s2); s2 = fmaf(a.w, v.w, s2);
                    }
                    float de = fmaf(-2.f, s2, g_cbsq[k] + xsv);
                    if (de < bestv || (de == bestv && k < bestk)) { bestv = de; bestk = k; }
                }
            }
        }
    }
    bv4[q * 64 + px] = bestv;
    bk4[q * 64 + px] = bestk;
    __syncthreads();

    if (t < 64) {
        float bv = bv4[t]; int bk = bk4[t];
#pragma unroll
        for (int qq = 1; qq < 4; qq++) {
            float v = bv4[qq * 64 + t]; int k = bk4[qq * 64 + t];
            if (v < bv || (v == bv && k < bk)) { bv = v; bk = k; }
        }
        sidx[t] = bk;
    }
    __syncthreads();

    // gather z_q (both copies)
    const int gpx = t & 63, dg = t >> 6;
    const float* crow = cb + (size_t)sidx[gpx] * DD;
    size_t ob = (size_t)b * DD * HW + hw0 + gpx;
#pragma unroll 8
    for (int dj = 0; dj < 64; dj++) {
        int d = dg * 64 + dj;
        float v = crow[d];
        out[OFF_ZQ1 + ob + (size_t)d * HW] = v;
        out[OFF_ZQ2 + ob + (size_t)d * HW] = v;
    }
}

extern "C" void kernel_launch(void* const* d_in, const int* in_sizes, int n_in,
                              void* d_out, int out_size) {
    const float* z  = (const float*)d_in[0];
    const float* cb = (const float*)d_in[1];
    float* out = (float*)d_out;

    cudaFuncSetAttribute(vq_gemm, cudaFuncAttributeMaxDynamicSharedMemorySize, SMEM_BYTES);

    vq_prep<<<512, 256>>>(z);
    vq_packB<<<256, 256>>>(cb);
    vq_cbsq<<<KK / 8 / 8, 256>>>(cb);
    vq_gemm<<<dim3(256, NTILES), 256, SMEM_BYTES>>>(cb, out);
    vq_rescore<<<NN / 64, 256>>>(cb, out);
}

// round 17
// speedup vs baseline: 1.6439x; 1.6439x over previous
#include <cuda_runtime.h>
#include <cstdint>

// Problem constants
#define DD   256
#define HW   4096
#define NN   32768
#define KK   8192
#define NTILES 64          // K tiles of 128 codes
#define EPS  6e-4f

// Scratch (no cudaMalloc allowed)
__device__ __align__(16) uint32_t g_Ah[(size_t)NN * DD / 2];  // bf16 frag-packed A (16 MB)
__device__ __align__(16) uint32_t g_Bh[(size_t)KK * DD / 2];  // bf16 frag-packed B (4 MB)
__device__ __align__(16) float g_X[(size_t)NN * DD];          // row-major pixels (32 MB)
__device__ __align__(16) float g_cbsq[KK];
__device__ float g_xsq[NN];
__device__ float g_pv[NTILES * NN];                    // per-(tile,pixel) tc-min
__device__ ulonglong2 g_mask[(size_t)NTILES * NN];     // 128-bit candidate masks (32 MB)

#define OFF_ZQ1 ((size_t)0)
#define OFF_ZQ2 ((size_t)NN * DD)
#define OFF_LOG ((size_t)2 * NN * DD)

#define MBA_OFF 65536                  // after 4 x 16KB stages: full[4], empty[4]
#define SMEM_BYTES 67136               // + fv(256) + pvw(128) floats

// ---------------- helpers ----------------
__device__ __forceinline__ uint32_t smem_u32(const void* p) {
    uint32_t a;
    asm("{ .reg .u64 t; cvta.to.shared.u64 t, %1; cvt.u32.u64 %0, t; }" : "=r"(a) : "l"(p));
    return a;
}
__device__ __forceinline__ uint32_t pack_bf16x2(float lo, float hi) {
    uint32_t r;
    asm("cvt.rn.bf16x2.f32 %0, %1, %2;" : "=r"(r) : "f"(hi), "f"(lo));
    return r;
}

// bulk async copy gmem->smem, completion via mbarrier complete_tx
__device__ __forceinline__ void bulk_cp(uint32_t dst, const void* src,
                                        uint32_t bytes, uint32_t mbar) {
    asm volatile(
        "cp.async.bulk.shared::cluster.global.mbarrier::complete_tx::bytes "
        "[%0], [%1], %2, [%3];"
        :: "r"(dst), "l"(src), "r"(bytes), "r"(mbar) : "memory");
}
#define MBARRIER_INIT(addr, count) \
    asm volatile("mbarrier.init.shared.b64 [%0], %1;" \
        :: "r"((uint32_t)(addr)), "r"((uint32_t)(count)) : "memory")
#define MBARRIER_EXPECT_TX(addr, bytes) \
    asm volatile("mbarrier.arrive.expect_tx.shared.b64 _, [%0], %1;" \
        :: "r"((uint32_t)(addr)), "r"((uint32_t)(bytes)) : "memory")
#define MBARRIER_ARRIVE(addr) \
    asm volatile("mbarrier.arrive.release.cta.shared.b64 _, [%0];" \
        :: "r"((uint32_t)(addr)) : "memory")
#define MBARRIER_WAIT_PARITY(mbar_smem_addr, phase_parity) do { \
    uint32_t _mbar = (uint32_t)(mbar_smem_addr); \
    uint32_t _parity = (uint32_t)(phase_parity); \
    uint32_t _done; \
    asm volatile( \
        "{\n\t.reg .pred p;\n\t" \
        "mbarrier.try_wait.parity.acquire.cta.shared::cta.b64 p, [%1], %2;\n\t" \
        "selp.b32 %0, 1, 0, p;\n\t}" \
        : "=r"(_done) : "r"(_mbar), "r"(_parity) : "memory"); \
    if (!_done) { \
        asm volatile( \
            "{\n\t.reg .pred P1;\n\t" \
            "WAIT_LOOP_%=:\n\t" \
            "mbarrier.try_wait.parity.acquire.cta.shared::cta.b64 P1, [%0], %1, 0x989680;\n\t" \
            "@P1 bra.uni WAIT_DONE_%=;\n\t" \
            "bra.uni WAIT_LOOP_%=;\n\t" \
            "WAIT_DONE_%=:\n\t}" \
            :: "r"(_mbar), "r"(_parity) : "memory"); \
    } \
} while(0)

// bf16 mma: D = A(16x16 row) * B(16x8 col) + D, fp32 accum
__device__ __forceinline__ void mma_bf16(float* c, const uint32_t* a, const uint32_t* b) {
    asm volatile(
        "mma.sync.aligned.m16n8k16.row.col.f32.bf16.bf16.f32 "
        "{%0,%1,%2,%3}, {%4,%5,%6,%7}, {%8,%9}, {%0,%1,%2,%3};"
        : "+f"(c[0]), "+f"(c[1]), "+f"(c[2]), "+f"(c[3])
        : "r"(a[0]), "r"(a[1]), "r"(a[2]), "r"(a[3]), "r"(b[0]), "r"(b[1]));
}

// swizzled float index inside the [128 px][128 col] staging buffer
__device__ __forceinline__ int stg_idx(int px, int col) {
    return px * 128 + (((col >> 2) ^ (px & 7)) << 2) + (col & 3);
}

// ---------------- prep kernels ----------------

// Per block: 64 pixels. Emits g_X rows + bf16 fragment-packed g_Ah + g_xsq.
__global__ void vq_prep(const float* __restrict__ z) {
    __shared__ float s[64 * 257];
    __shared__ float ps[256];
    const int t = threadIdx.x;
    const int mtile = blockIdx.x >> 1, wm = blockIdx.x & 1;
    const int p0 = mtile * 128 + wm * 64;
    const int b = p0 >> 12, hw0 = p0 & 4095;
    const float* zb = z + (size_t)b * DD * HW + hw0;
#pragma unroll 8
    for (int i = 0; i < 64; i++) {
        int idx = i * 256 + t;
        int d = idx >> 6, px = idx & 63;
        s[px * 257 + d] = zb[(size_t)d * HW + px];
    }
    __syncthreads();
    // xsq: 4-way split per pixel (uniform per-pixel shift -> argmin-safe)
    {
        int p = t >> 2, q = t & 3;
        const float* row = s + p * 257 + q * 64;
        float acc = 0.f;
#pragma unroll 8
        for (int i = 0; i < 64; i++) acc = fmaf(row[i], row[i], acc);
        ps[t] = acc;
    }
    // row-major copy
    float* gx = g_X + (size_t)p0 * DD;
#pragma unroll 8
    for (int i = 0; i < 64; i++)
        gx[(size_t)i * DD + t] = s[i * 257 + t];
    // bf16 fragment pack: items = [c16(16)][mi(4)][lane(32)][r(4)] = 8192
#pragma unroll
    for (int w = 0; w < 32; w++) {
        int item = w * 256 + t;
        int r = item & 3;
        int lane = (item >> 2) & 31;
        int mi = (item >> 7) & 3;
        int c16 = item >> 9;                 // k-step of 16
        int pxl = mi * 16 + (lane >> 2) + (r & 1) * 8;
        int k = c16 * 16 + (lane & 3) * 2 + (r >> 1) * 8;
        uint32_t v = pack_bf16x2(s[pxl * 257 + k], s[pxl * 257 + k + 1]);
        g_Ah[((size_t)(mtile * 8 + (c16 >> 1)) * 2 + (c16 & 1)) * 1024
             + ((wm * 4 + mi) * 32 + lane) * 4 + r] = v;
    }
    __syncthreads();
    if (t < 64)
        g_xsq[p0 + t] = ((ps[t * 4] + ps[t * 4 + 1]) + ps[t * 4 + 2]) + ps[t * 4 + 3];
}

// g_Bh: per (ntile, chunk32): [ks(2)][nf(16)][lane(32)][r(2)] uint32 = 8KB
__global__ void vq_packB(const float* __restrict__ cb) {
    const int t = threadIdx.x;
    const int nt = blockIdx.x >> 3, ch = blockIdx.x & 7;
    const int k0 = nt * 128;
    uint32_t* dst = g_Bh + (size_t)blockIdx.x * 2048;
#pragma unroll
    for (int w = 0; w < 8; w++) {
        int item = w * 256 + t;              // 0..2047
        int r = item & 1;
        int lane = (item >> 1) & 31;
        int nf = (item >> 6) & 15;
        int ks = item >> 10;
        int code = k0 + nf * 8 + (lane >> 2);
        int k = ch * 32 + ks * 16 + (lane & 3) * 2 + r * 8;
        const float* src = cb + (size_t)code * DD + k;
        dst[ks * 1024 + (nf * 32 + lane) * 2 + r] = pack_bf16x2(src[0], src[1]);
    }
}

// warp-per-code ||c||^2
__global__ void vq_cbsq(const float* __restrict__ cb) {
    int w = (blockIdx.x * 256 + threadIdx.x) >> 5;
    int lane = threadIdx.x & 31;
    const float* r = cb + (size_t)w * DD + lane;
    float s = 0.f;
#pragma unroll
    for (int i = 0; i < 8; i++) { float v = r[i * 32]; s = fmaf(v, v, s); }
#pragma unroll
    for (int o = 16; o > 0; o >>= 1)
        s += __shfl_xor_sync(0xffffffffu, s, o);
    if (lane == 0) g_cbsq[w] = s;
}

// ---------------- bf16 mma.sync GEMM + logits + tile min/mask ----------------
// grid (256 m-tiles, 64 n-tiles), 256 threads (8 warps: 2 m x 4 n), 2 CTAs/SM
// Barrier-free mainloop: 4-stage full/empty mbarrier ring, bulk_cp fills.
__global__ void __launch_bounds__(256, 2)
vq_gemm(const float* __restrict__ cb, float* __restrict__ out) {
    extern __shared__ float sm[];
    const int tid = threadIdx.x, lane = tid & 31, wid = tid >> 5;
    const int wm = wid & 1, wn = wid >> 1;
    const int mtile = blockIdx.x, ntile = blockIdx.y;
    const int n0 = mtile * 128, k0 = ntile * 128;
    const int b = n0 >> 12, hw0 = n0 & 4095;
    const uint32_t sb = smem_u32(sm);

    const uint32_t* gAb = g_Ah + (size_t)mtile * 8 * 2048;
    const uint32_t* gBb = g_Bh + (size_t)ntile * 8 * 2048;

    if (tid == 0) {
#pragma unroll
        for (int s = 0; s < 4; s++) {
            MBARRIER_INIT(sb + MBA_OFF + s * 8, 1);        // full (tx-based)
            MBARRIER_INIT(sb + MBA_OFF + 32 + s * 8, 8);   // empty (8 warp arrivals)
        }
    }
    __syncthreads();

    auto issue = [&](int c) {
        uint32_t base = sb + (uint32_t)(c & 3) * 16384u;
        uint32_t mb = sb + MBA_OFF + (c & 3) * 8;
        MBARRIER_EXPECT_TX(mb, 16384u);
        bulk_cp(base,        gAb + (size_t)c * 2048, 8192u, mb);
        bulk_cp(base + 8192, gBb + (size_t)c * 2048, 8192u, mb);
    };
    if (tid == 0) { issue(0); issue(1); issue(2); issue(3); }

    float acc[4][4][4];
#pragma unroll
    for (int i = 0; i < 4; i++)
#pragma unroll
        for (int j = 0; j < 4; j++)
#pragma unroll
            for (int r = 0; r < 4; r++) acc[i][j][r] = 0.f;

#pragma unroll
    for (int c = 0; c < 8; c++) {
        const int s = c & 3;
        const int par = (c >> 2) & 1;
        MBARRIER_WAIT_PARITY(sb + MBA_OFF + s * 8, par);
        const uint32_t* As = (const uint32_t*)sm + s * 4096;
        const uint32_t* Bs = As + 2048;
#pragma unroll
        for (int ks = 0; ks < 2; ks++) {
            uint4 af[4]; uint2 bf[4];
#pragma unroll
            for (int i = 0; i < 4; i++)
                af[i] = *(const uint4*)(As + ks * 1024 + ((wm * 4 + i) * 32 + lane) * 4);
#pragma unroll
            for (int j = 0; j < 4; j++)
                bf[j] = *(const uint2*)(Bs + ks * 1024 + ((wn * 4 + j) * 32 + lane) * 2);
#pragma unroll
            for (int i = 0; i < 4; i++)
#pragma unroll
                for (int j = 0; j < 4; j++)
                    mma_bf16(acc[i][j], (const uint32_t*)&af[i], (const uint32_t*)&bf[j]);
        }
        if (lane == 0) MBARRIER_ARRIVE(sb + MBA_OFF + 32 + s * 8);
        if (c + 4 < 8 && tid == 0) {
            MBARRIER_WAIT_PARITY(sb + MBA_OFF + 32 + s * 8, par);
            issue(c + 4);
        }
    }
    __syncthreads();

    // phase 1: dump accumulators into smem staging [128 px][128 col] (swizzled)
#pragma unroll
    for (int i = 0; i < 4; i++) {
#pragma unroll
        for (int j = 0; j < 4; j++) {
            int px = wm * 64 + i * 16 + (lane >> 2);
            int col = wn * 32 + j * 8 + 2 * (lane & 3);
            *(float2*)&sm[stg_idx(px,     col)] = make_float2(acc[i][j][0], acc[i][j][1]);
            *(float2*)&sm[stg_idx(px + 8, col)] = make_float2(acc[i][j][2], acc[i][j][3]);
        }
    }
    __syncthreads();

    // phase 2: dist + coalesced logit stores + per-pixel min
    const int px = tid & 127, half = tid >> 7;
    const float xsv = g_xsq[n0 + px];
    float* lb = out + OFF_LOG + ((size_t)b * KK + k0) * HW + hw0 + px;
    float bv = __int_as_float(0x7f800000);
#pragma unroll
    for (int it = 0; it < 16; it++) {
        int cg = half * 16 + it;
        float4 dv = *(const float4*)&sm[px * 128 + ((cg ^ (px & 7)) << 2)];
        float4 cq = *(const float4*)&g_cbsq[k0 + cg * 4];
        float d0 = fmaf(-2.f, dv.x, cq.x + xsv);
        float d1 = fmaf(-2.f, dv.y, cq.y + xsv);
        float d2 = fmaf(-2.f, dv.z, cq.z + xsv);
        float d3 = fmaf(-2.f, dv.w, cq.w + xsv);
        bv = fminf(bv, fminf(fminf(d0, d1), fminf(d2, d3)));
        __stcs(lb + (size_t)(cg * 4 + 0) * HW, -d0);
        __stcs(lb + (size_t)(cg * 4 + 1) * HW, -d1);
        __stcs(lb + (size_t)(cg * 4 + 2) * HW, -d2);
        __stcs(lb + (size_t)(cg * 4 + 3) * HW, -d3);
    }
    float* fv  = sm + 16400;   // [256]
    float* pvw = sm + 16656;   // [128] combined per-pixel min
    fv[tid] = bv;
    __syncthreads();
    if (tid < 128) {
        float comb = fminf(fv[tid], fv[128 + tid]);
        g_pv[(size_t)ntile * NN + n0 + tid] = comb;
        pvw[tid] = comb;
    }
    __syncthreads();

    // phase 3: candidate bitmask (codes with dtc <= tile_min + EPS)
    const float thr = pvw[px] + EPS;
    unsigned long long m64 = 0;
#pragma unroll
    for (int it = 0; it < 16; it++) {
        int cg = half * 16 + it;
        float4 dv = *(const float4*)&sm[px * 128 + ((cg ^ (px & 7)) << 2)];
        float4 cq = *(const float4*)&g_cbsq[k0 + cg * 4];
        float d0 = fmaf(-2.f, dv.x, cq.x + xsv);
        float d1 = fmaf(-2.f, dv.y, cq.y + xsv);
        float d2 = fmaf(-2.f, dv.z, cq.z + xsv);
        float d3 = fmaf(-2.f, dv.w, cq.w + xsv);
        if (d0 <= thr) m64 |= 1ull << (it * 4 + 0);
        if (d1 <= thr) m64 |= 1ull << (it * 4 + 1);
        if (d2 <= thr) m64 |= 1ull << (it * 4 + 2);
        if (d3 <= thr) m64 |= 1ull << (it * 4 + 3);
    }
    ((unsigned long long*)g_mask)[((size_t)ntile * NN + n0 + px) * 2 + half] = m64;
}

// ---------------- exact rescore of masked candidates + gather ----------------
// grid 512 blocks x 256 threads; 64 px/block, 4 threads per pixel (16 tiles each)
__global__ void __launch_bounds__(256)
vq_rescore(const float* __restrict__ cb, float* __restrict__ out) {
    __shared__ float Xs[64 * 260];
    __shared__ float lmv[4 * 64];
    __shared__ float bv4[4 * 64];
    __shared__ int   bk4[4 * 64];
    __shared__ int   sidx[64];
    const int t = threadIdx.x;
    const int n0 = blockIdx.x * 64;
    const int b = n0 >> 12, hw0 = n0 & 4095;
    const int px = t & 63, q = t >> 6;      // 4 threads per pixel
    const int n = n0 + px;

    const float4* gx = (const float4*)(g_X + (size_t)n0 * DD);
#pragma unroll
    for (int i = 0; i < 16; i++) {
        int idx = t + i * 256;
        int ppx = idx >> 6, qq = idx & 63;
        *(float4*)&Xs[ppx * 260 + qq * 4] = gx[ppx * 64 + qq];
    }

    // local min over this thread's 16 tiles
    float lm = __int_as_float(0x7f800000);
#pragma unroll
    for (int i = 0; i < 16; i++)
        lm = fminf(lm, g_pv[(size_t)(q * 16 + i) * NN + n]);
    lmv[q * 64 + px] = lm;
    __syncthreads();
    const float thresh = fminf(fminf(lmv[px], lmv[64 + px]),
                               fminf(lmv[128 + px], lmv[192 + px])) + EPS;

    // scan own 16 tiles for candidates, exact rescore
    const float xsv = g_xsq[n];
    const float* xr = &Xs[px * 260];
    float bestv = __int_as_float(0x7f800000);
    int bestk = 0x7fffffff;
#pragma unroll
    for (int i = 0; i < 16; i++) {
        int s = q * 16 + i;
        if (g_pv[(size_t)s * NN + n] <= thresh) {
            ulonglong2 mk = g_mask[(size_t)s * NN + n];
#pragma unroll
            for (int w = 0; w < 2; w++) {
                unsigned long long mw = w ? mk.y : mk.x;
                while (mw) {
                    int j = __ffsll(mw) - 1;
                    mw &= mw - 1;
                    int k = s * 128 + w * 64 + j;
                    const float4* cv = (const float4*)(cb + (size_t)k * DD);
                    float s2 = 0.f;
#pragma unroll 8
                    for (int qq = 0; qq < 64; qq++) {
                        float4 a = *(const float4*)&xr[qq * 4];
                        float4 v = cv[qq];
                        s2 = fmaf(a.x, v.x, s2); s2 = fmaf(a.y, v.y, s2);
                        s2 = fmaf(a.z, v.z, s2); s2 = fmaf(a.w, v.w, s2);
                    }
                    float de = fmaf(-2.f, s2, g_cbsq[k] + xsv);
                    if (de < bestv || (de == bestv && k < bestk)) { bestv = de; bestk = k; }
                }
            }
        }
    }
    bv4[q * 64 + px] = bestv;
    bk4[q * 64 + px] = bestk;
    __syncthreads();

    if (t < 64) {
        float bv = bv4[t]; int bk = bk4[t];
#pragma unroll
        for (int qq = 1; qq < 4; qq++) {
            float v = bv4[qq * 64 + t]; int k = bk4[qq * 64 + t];
            if (v < bv || (v == bv && k < bk)) { bv = v; bk = k; }
        }
        sidx[t] = bk;
    }
    __syncthreads();

    // gather z_q (both copies)
    const int gpx = t & 63, dg = t >> 6;
    const float* crow = cb + (size_t)sidx[gpx] * DD;
    size_t ob = (size_t)b * DD * HW + hw0 + gpx;
#pragma unroll 8
    for (int dj = 0; dj < 64; dj++) {
        int d = dg * 64 + dj;
        float v = crow[d];
        out[OFF_ZQ1 + ob + (size_t)d * HW] = v;
        out[OFF_ZQ2 + ob + (size_t)d * HW] = v;
    }
}

extern "C" void kernel_launch(void* const* d_in, const int* in_sizes, int n_in,
                              void* d_out, int out_size) {
    const float* z  = (const float*)d_in[0];
    const float* cb = (const float*)d_in[1];
    float* out = (float*)d_out;

    cudaFuncSetAttribute(vq_gemm, cudaFuncAttributeMaxDynamicSharedMemorySize, SMEM_BYTES);

    vq_prep<<<512, 256>>>(z);
    vq_packB<<<512, 256>>>(cb);
    vq_cbsq<<<KK / 8 / 8, 256>>>(cb);
    vq_gemm<<<dim3(256, NTILES), 256, SMEM_BYTES>>>(cb, out);
    vq_rescore<<<NN / 64, 256>>>(cb, out);
}